// round 3
// baseline (speedup 1.0000x reference)
#include <cuda_runtime.h>
#include <cstdint>

#define N_NODES 100000
#define N_EDGES 1600000
#define F_IN    128
#define F_H     64
#define F_OUT   16

// Scratch (allocation-free rule: __device__ globals)
__device__ float g_H1[N_NODES * F_H];     // X @ W1
__device__ float g_AGG1[N_NODES * F_H];   // scatter target layer 1
__device__ float g_H2[N_NODES * F_OUT];   // relu(agg1+b1) @ W2

// ---------------------------------------------------------------------------
// K0: zero AGG1, init out to b2 (out is poisoned to 0xAA by harness)
// ---------------------------------------------------------------------------
__global__ void k_init(float* __restrict__ out, const float* __restrict__ b2) {
    int i = blockIdx.x * blockDim.x + threadIdx.x;
    int stride = gridDim.x * blockDim.x;
    for (int j = i; j < N_NODES * F_H; j += stride) g_AGG1[j] = 0.0f;
    for (int j = i; j < N_NODES * F_OUT; j += stride) out[j] = b2[j & (F_OUT - 1)];
}

// ---------------------------------------------------------------------------
// K1: H1 = X @ W1   (100000 x 128) @ (128 x 64)
// 32-row x 64-col tile per 256-thread block; smem-staged X tile + full W1.
// ---------------------------------------------------------------------------
__global__ __launch_bounds__(256) void k_gemm1(const float* __restrict__ X,
                                               const float* __restrict__ W1) {
    __shared__ float Xs[32][128];   // 16 KB
    __shared__ float Ws[128][64];   // 32 KB  (total 48 KB static)
    const int t  = threadIdx.x;
    const int r0 = blockIdx.x * 32;

    // load W1: 8192 floats = 2048 float4
    {
        const float4* W4  = (const float4*)W1;
        float4*       Ws4 = (float4*)Ws;
#pragma unroll
        for (int i = 0; i < 8; i++) Ws4[i * 256 + t] = W4[i * 256 + t];
    }
    // load X tile: 32 rows * 32 float4 = 1024 float4
    {
        float4* Xs4 = (float4*)Xs;
#pragma unroll
        for (int i = 0; i < 4; i++) {
            int idx = i * 256 + t;
            int row = idx >> 5, c4 = idx & 31;
            float4 v = make_float4(0.f, 0.f, 0.f, 0.f);
            if (r0 + row < N_NODES)
                v = *(const float4*)(X + (size_t)(r0 + row) * F_IN + c4 * 4);
            Xs4[idx] = v;
        }
    }
    __syncthreads();

    const int ty = t >> 4;   // 0..15 -> rows ty*2, ty*2+1
    const int tx = t & 15;   // cols tx*4 .. tx*4+3
    float acc0[4] = {0, 0, 0, 0};
    float acc1[4] = {0, 0, 0, 0};

#pragma unroll 8
    for (int k = 0; k < 128; k++) {
        float4 b = *(const float4*)&Ws[k][tx * 4];
        float a0 = Xs[ty * 2 + 0][k];
        float a1 = Xs[ty * 2 + 1][k];
        acc0[0] = fmaf(a0, b.x, acc0[0]);
        acc0[1] = fmaf(a0, b.y, acc0[1]);
        acc0[2] = fmaf(a0, b.z, acc0[2]);
        acc0[3] = fmaf(a0, b.w, acc0[3]);
        acc1[0] = fmaf(a1, b.x, acc1[0]);
        acc1[1] = fmaf(a1, b.y, acc1[1]);
        acc1[2] = fmaf(a1, b.z, acc1[2]);
        acc1[3] = fmaf(a1, b.w, acc1[3]);
    }

    int r = r0 + ty * 2;
    if (r < N_NODES)
        *(float4*)(g_H1 + (size_t)r * F_H + tx * 4) =
            make_float4(acc0[0], acc0[1], acc0[2], acc0[3]);
    if (r + 1 < N_NODES)
        *(float4*)(g_H1 + (size_t)(r + 1) * F_H + tx * 4) =
            make_float4(acc1[0], acc1[1], acc1[2], acc1[3]);
}

// ---------------------------------------------------------------------------
// K2: per edge: AGG1[dst] += H1[src] * w    (64 floats -> 16 lanes x float4)
// ---------------------------------------------------------------------------
__global__ __launch_bounds__(256) void k_scatter1(const int* __restrict__ src,
                                                  const int* __restrict__ dst,
                                                  const float* __restrict__ w) {
    const long long idx = (long long)blockIdx.x * 256 + threadIdx.x;
    const int e    = (int)(idx >> 4);
    const int part = (int)idx & 15;
    if (e >= N_EDGES) return;
    const int   s  = src[e];
    const int   d  = dst[e];
    const float ww = w[e];
    const float4 v = *(const float4*)(g_H1 + (size_t)s * F_H + part * 4);
    float* p = g_AGG1 + (size_t)d * F_H + part * 4;
    asm volatile("red.global.add.v4.f32 [%0], {%1,%2,%3,%4};" ::
                 "l"(p), "f"(v.x * ww), "f"(v.y * ww), "f"(v.z * ww), "f"(v.w * ww)
                 : "memory");
}

// ---------------------------------------------------------------------------
// K3: H2 = relu(AGG1 + b1) @ W2   (100000 x 64) @ (64 x 16)
// 64-row tile per 256-thread block.
// ---------------------------------------------------------------------------
__global__ __launch_bounds__(256) void k_gemm2(const float* __restrict__ b1,
                                               const float* __restrict__ W2) {
    __shared__ float Hs[64][65];   // padded stride to dodge bank conflicts
    __shared__ float Ws2[64 * 16];
    const int t  = threadIdx.x;
    const int r0 = blockIdx.x * 64;

    // load W2 (1024 floats)
#pragma unroll
    for (int i = 0; i < 4; i++) Ws2[i * 256 + t] = W2[i * 256 + t];

    // load + bias + relu the h tile: 64 rows * 64 cols
#pragma unroll
    for (int i = 0; i < 16; i++) {
        int idx = i * 256 + t;
        int row = idx >> 6, col = idx & 63;
        float v = 0.f;
        if (r0 + row < N_NODES)
            v = fmaxf(g_AGG1[(size_t)(r0 + row) * F_H + col] + b1[col], 0.f);
        Hs[row][col] = v;
    }
    __syncthreads();

    const int ty = t >> 2;  // row 0..63
    const int tx = t & 3;   // col group
    float acc[4] = {0, 0, 0, 0};
#pragma unroll 8
    for (int k = 0; k < 64; k++) {
        float  a = Hs[ty][k];
        float4 b = *(const float4*)&Ws2[k * 16 + tx * 4];
        acc[0] = fmaf(a, b.x, acc[0]);
        acc[1] = fmaf(a, b.y, acc[1]);
        acc[2] = fmaf(a, b.z, acc[2]);
        acc[3] = fmaf(a, b.w, acc[3]);
    }
    int r = r0 + ty;
    if (r < N_NODES)
        *(float4*)(g_H2 + (size_t)r * F_OUT + tx * 4) =
            make_float4(acc[0], acc[1], acc[2], acc[3]);
}

// ---------------------------------------------------------------------------
// K4: per edge: out[dst] += H2[src] * w   (16 floats -> 4 lanes x float4)
// ---------------------------------------------------------------------------
__global__ __launch_bounds__(256) void k_scatter2(const int* __restrict__ src,
                                                  const int* __restrict__ dst,
                                                  const float* __restrict__ w,
                                                  float* __restrict__ out) {
    const long long idx = (long long)blockIdx.x * 256 + threadIdx.x;
    const int e    = (int)(idx >> 2);
    const int part = (int)idx & 3;
    if (e >= N_EDGES) return;
    const int   s  = src[e];
    const int   d  = dst[e];
    const float ww = w[e];
    const float4 v = *(const float4*)(g_H2 + (size_t)s * F_OUT + part * 4);
    float* p = out + (size_t)d * F_OUT + part * 4;
    asm volatile("red.global.add.v4.f32 [%0], {%1,%2,%3,%4};" ::
                 "l"(p), "f"(v.x * ww), "f"(v.y * ww), "f"(v.z * ww), "f"(v.w * ww)
                 : "memory");
}

// ---------------------------------------------------------------------------
// Inputs (metadata order): 0:X 1:edge_weight 2:W1 3:b1 4:W2 5:b2 6:edge_src 7:edge_dst
// ---------------------------------------------------------------------------
extern "C" void kernel_launch(void* const* d_in, const int* in_sizes, int n_in,
                              void* d_out, int out_size) {
    const float* X  = (const float*)d_in[0];
    const float* ew = (const float*)d_in[1];
    const float* W1 = (const float*)d_in[2];
    const float* b1 = (const float*)d_in[3];
    const float* W2 = (const float*)d_in[4];
    const float* b2 = (const float*)d_in[5];
    const int* esrc = (const int*)d_in[6];
    const int* edst = (const int*)d_in[7];
    float* out = (float*)d_out;

    k_init<<<2048, 256>>>(out, b2);
    k_gemm1<<<(N_NODES + 31) / 32, 256>>>(X, W1);
    k_scatter1<<<(N_EDGES * 16) / 256, 256>>>(esrc, edst, ew);
    k_gemm2<<<(N_NODES + 63) / 64, 256>>>(b1, W2);
    k_scatter2<<<(N_EDGES * 4) / 256, 256>>>(esrc, edst, ew, out);
}